// round 8
// baseline (speedup 1.0000x reference)
#include <cuda_runtime.h>

// DfOp: out[b,t,f] = sum_{i=0..4} spec[b, t+i-4, f] * coefs[b, i, t, f] (complex) for f < 96
//       out[b,t,f] = spec[b,t,f]                                                 for f >= 96
// spec:  (8, 1, 4096, 481, 2) f32, coefs: (8, 5, 4096, 96, 2) f32
//
// Block = 256 threads handles FOUR consecutive rows (r0 = 4*bid, .., r0+3).
//  tid 0..191  : filter; thread covers 2 bins of one row
//                (5x LDG.128 coef + 10x LDG.64 spec = 160 B in flight)
//  tid 192..255: copy float region [192,962) of two rows each
//                (12x LDG.128 = 192 B in flight)

#define DF_B  8
#define DF_T  4096
#define DF_F  481
#define DF_NF 96
#define DF_FS 5
#define ROW_FLOATS (2 * DF_F)   // 962

__global__ __launch_bounds__(256) void df_op_kernel(
    const float* __restrict__ specf,
    const float4* __restrict__ coefs4,   // coefs viewed as float4 = 2 complex bins
    float* __restrict__ outf)
{
    const int bid = blockIdx.x;
    const int r0  = bid << 2;            // first of 4 rows (multiple of 4)
    const int tid = threadIdx.x;

    if (tid < 192) {
        // ---------------- filter path: 2 bins per thread ----------------
        const int row_off = tid / 48;               // 0..3
        const int j       = tid - 48 * row_off;     // 0..47 -> bins 2j, 2j+1
        const int row     = r0 + row_off;
        const int t       = row & (DF_T - 1);
        const int b       = row >> 12;
        const long rowf   = (long)row * ROW_FLOATS;

        // coefs float4 index for (b, i, t, bin-pair j): ((b*5+i)*T + t)*48 + j
        const int cbase = ((b * DF_FS) * DF_T + t) * 48 + j;
        const float* __restrict__ sp = specf + rowf + 4 * j;

        float re0 = 0.f, im0 = 0.f, re1 = 0.f, im1 = 0.f;
        if (t >= DF_FS - 1) {
            #pragma unroll
            for (int i = 0; i < DF_FS; i++) {
                float4 c = __ldcs(coefs4 + cbase + i * (DF_T * 48));
                const float* s = sp + (long)(i - (DF_FS - 1)) * ROW_FLOATS;
                float2 sa = *(const float2*)(s);
                float2 sb = *(const float2*)(s + 2);
                re0 = fmaf( sa.x, c.x, re0); re0 = fmaf(-sa.y, c.y, re0);
                im0 = fmaf( sa.x, c.y, im0); im0 = fmaf( sa.y, c.x, im0);
                re1 = fmaf( sb.x, c.z, re1); re1 = fmaf(-sb.y, c.w, re1);
                im1 = fmaf( sb.x, c.w, im1); im1 = fmaf( sb.y, c.z, im1);
            }
        } else {
            #pragma unroll
            for (int i = 0; i < DF_FS; i++) {
                if (t + i >= DF_FS - 1) {
                    float4 c = __ldcs(coefs4 + cbase + i * (DF_T * 48));
                    const float* s = sp + (long)(i - (DF_FS - 1)) * ROW_FLOATS;
                    float2 sa = *(const float2*)(s);
                    float2 sb = *(const float2*)(s + 2);
                    re0 = fmaf( sa.x, c.x, re0); re0 = fmaf(-sa.y, c.y, re0);
                    im0 = fmaf( sa.x, c.y, im0); im0 = fmaf( sa.y, c.x, im0);
                    re1 = fmaf( sb.x, c.z, re1); re1 = fmaf(-sb.y, c.w, re1);
                    im1 = fmaf( sb.x, c.w, im1); im1 = fmaf( sb.y, c.z, im1);
                }
            }
        }
        __stcs((float2*)(outf + rowf + 4 * j),     make_float2(re0, im0));
        __stcs((float2*)(outf + rowf + 4 * j + 2), make_float2(re1, im1));
    } else {
        // ---------------- copy path: 2 rows per thread-group of 32 ----------------
        const int c    = tid - 192;                   // 0..63
        const int pair = c >> 5;                      // 0 -> rows r0,r0+1 ; 1 -> r0+2,r0+3
        const int j    = c & 31;                      // 0..31
        const long rfA = (long)(r0 + 2 * pair) * ROW_FLOATS;   // even row: %4 == 0
        const long rfB = rfA + ROW_FLOATS;                     // odd row:  %4 == 2

        const float4* __restrict__ s0 = (const float4*)(specf + rfA + 192); // aligned
        const float4* __restrict__ s1 = (const float4*)(specf + rfB + 194); // aligned
        float4* __restrict__ d0 = (float4*)(outf + rfA + 192);
        float4* __restrict__ d1 = (float4*)(outf + rfB + 194);

        // 12 front-batched LDG.128 per thread
        float4 a0 = __ldcs(s0 + j);
        float4 a1 = __ldcs(s0 + j + 32);
        float4 a2 = __ldcs(s0 + j + 64);
        float4 a3 = __ldcs(s0 + j + 96);
        float4 a4 = __ldcs(s0 + j + 128);
        float4 a5 = __ldcs(s0 + j + 160);
        float4 b0 = __ldcs(s1 + j);
        float4 b1 = __ldcs(s1 + j + 32);
        float4 b2 = __ldcs(s1 + j + 64);
        float4 b3 = __ldcs(s1 + j + 96);
        float4 b4 = __ldcs(s1 + j + 128);
        float4 b5 = __ldcs(s1 + j + 160);

        __stcs(d0 + j,       a0);
        __stcs(d0 + j + 32,  a1);
        __stcs(d0 + j + 64,  a2);
        __stcs(d0 + j + 96,  a3);
        __stcs(d0 + j + 128, a4);
        __stcs(d0 + j + 160, a5);
        __stcs(d1 + j,       b0);
        __stcs(d1 + j + 32,  b1);
        __stcs(d1 + j + 64,  b2);
        __stcs(d1 + j + 96,  b3);
        __stcs(d1 + j + 128, b4);
        __stcs(d1 + j + 160, b5);

        // leftover float2s: even row at +960, odd row at +192
        if (j == 0) {
            float2 v = __ldcs((const float2*)(specf + rfA + 960));
            __stcs((float2*)(outf + rfA + 960), v);
        } else if (j == 1) {
            float2 v = __ldcs((const float2*)(specf + rfB + 192));
            __stcs((float2*)(outf + rfB + 192), v);
        }
    }
}

extern "C" void kernel_launch(void* const* d_in, const int* in_sizes, int n_in,
                              void* d_out, int out_size)
{
    const float*  spec   = (const float*)d_in[0];
    const float4* coefs4 = (const float4*)d_in[1];
    float* out = (float*)d_out;

    df_op_kernel<<<(DF_B * DF_T) / 4, 256>>>(spec, coefs4, out);
}

// round 9
// speedup vs baseline: 1.0352x; 1.0352x over previous
#include <cuda_runtime.h>

// DfOp: out[b,t,f] = sum_{i=0..4} spec[b, t+i-4, f] * coefs[b, i, t, f] (complex) for f < 96
//       out[b,t,f] = spec[b,t,f]                                                 for f >= 96
// spec:  (8, 1, 4096, 481, 2) f32, coefs: (8, 5, 4096, 96, 2) f32
//
// Block = 128 threads, TWO rows of the SAME parity: {4k,4k+2} (even bid) or
// {4k+1,4k+3} (odd bid). Row parity is block-uniform -> all alignment decisions
// are compile-time (template<PAR>), giving LDG.128 spec taps where the tap row
// base is 16B-aligned (row stride 962 alternates alignment by tap parity).
//  tid 0..95  : filter, 2 bins/thread (5x LDG.128 coef + 7-8 mixed spec loads)
//  tid 96..127: copy float region [192,962) of both rows (12x LDG.128)

#define DF_B  8
#define DF_T  4096
#define DF_F  481
#define DF_NF 96
#define DF_FS 5
#define ROW_FLOATS (2 * DF_F)   // 962

template<int PAR>
__device__ __forceinline__ void do_filter(
    const float* __restrict__ specf,
    const float4* __restrict__ coefs4,
    float* __restrict__ outf,
    int row, int j)
{
    const int t = row & (DF_T - 1);
    const int b = row >> 12;
    const long rowf = (long)row * ROW_FLOATS;
    const int cbase = ((b * DF_FS) * DF_T + t) * 48 + j;
    const float* __restrict__ sp = specf + rowf + 4 * j;

    float re0 = 0.f, im0 = 0.f, re1 = 0.f, im1 = 0.f;
    if (t >= DF_FS - 1) {
        #pragma unroll
        for (int i = 0; i < DF_FS; i++) {
            float4 c = __ldcs(coefs4 + cbase + i * (DF_T * 48));
            const float* s = sp + (long)(i - (DF_FS - 1)) * ROW_FLOATS;
            float2 sa, sb;
            if (((i ^ PAR) & 1) == 0) {
                // tap base 16B-aligned: one LDG.128 covers both bins
                float4 v = *(const float4*)s;
                sa = make_float2(v.x, v.y);
                sb = make_float2(v.z, v.w);
            } else {
                sa = *(const float2*)s;
                sb = *(const float2*)(s + 2);
            }
            re0 = fmaf( sa.x, c.x, re0); re0 = fmaf(-sa.y, c.y, re0);
            im0 = fmaf( sa.x, c.y, im0); im0 = fmaf( sa.y, c.x, im0);
            re1 = fmaf( sb.x, c.z, re1); re1 = fmaf(-sb.y, c.w, re1);
            im1 = fmaf( sb.x, c.w, im1); im1 = fmaf( sb.y, c.z, im1);
        }
    } else {
        #pragma unroll
        for (int i = 0; i < DF_FS; i++) {
            if (t + i >= DF_FS - 1) {
                float4 c = __ldcs(coefs4 + cbase + i * (DF_T * 48));
                const float* s = sp + (long)(i - (DF_FS - 1)) * ROW_FLOATS;
                float2 sa = *(const float2*)(s);
                float2 sb = *(const float2*)(s + 2);
                re0 = fmaf( sa.x, c.x, re0); re0 = fmaf(-sa.y, c.y, re0);
                im0 = fmaf( sa.x, c.y, im0); im0 = fmaf( sa.y, c.x, im0);
                re1 = fmaf( sb.x, c.z, re1); re1 = fmaf(-sb.y, c.w, re1);
                im1 = fmaf( sb.x, c.w, im1); im1 = fmaf( sb.y, c.z, im1);
            }
        }
    }
    if (PAR == 0) {
        // output base 16B-aligned: single STG.128
        __stcs((float4*)(outf + rowf + 4 * j), make_float4(re0, im0, re1, im1));
    } else {
        __stcs((float2*)(outf + rowf + 4 * j),     make_float2(re0, im0));
        __stcs((float2*)(outf + rowf + 4 * j + 2), make_float2(re1, im1));
    }
}

__global__ __launch_bounds__(128) void df_op_kernel(
    const float* __restrict__ specf,
    const float4* __restrict__ coefs4,
    float* __restrict__ outf)
{
    const int bid  = blockIdx.x;
    const int par  = bid & 1;
    const int base = ((bid >> 1) << 2) + par;   // rows: base, base+2 (same parity)
    const int tid  = threadIdx.x;

    if (tid < 96) {
        const int row = base + ((tid >= 48) ? 2 : 0);
        const int j   = (tid >= 48) ? tid - 48 : tid;   // 0..47 -> bins 2j, 2j+1
        if (par == 0) do_filter<0>(specf, coefs4, outf, row, j);
        else          do_filter<1>(specf, coefs4, outf, row, j);
    } else {
        // ---------------- copy path: floats [192,962) of both rows ----------------
        const int  j     = tid - 96;                    // 0..31
        const long rfA   = (long)base * ROW_FLOATS;
        const long rfB   = rfA + 2 * ROW_FLOATS;
        const int  start = 192 + 2 * par;               // 16B-aligned float4 base

        const float4* __restrict__ s0 = (const float4*)(specf + rfA + start);
        const float4* __restrict__ s1 = (const float4*)(specf + rfB + start);
        float4* __restrict__ d0 = (float4*)(outf + rfA + start);
        float4* __restrict__ d1 = (float4*)(outf + rfB + start);

        // 12 front-batched LDG.128 per thread
        float4 a0 = __ldcs(s0 + j);
        float4 a1 = __ldcs(s0 + j + 32);
        float4 a2 = __ldcs(s0 + j + 64);
        float4 a3 = __ldcs(s0 + j + 96);
        float4 a4 = __ldcs(s0 + j + 128);
        float4 a5 = __ldcs(s0 + j + 160);
        float4 b0 = __ldcs(s1 + j);
        float4 b1 = __ldcs(s1 + j + 32);
        float4 b2 = __ldcs(s1 + j + 64);
        float4 b3 = __ldcs(s1 + j + 96);
        float4 b4 = __ldcs(s1 + j + 128);
        float4 b5 = __ldcs(s1 + j + 160);

        __stcs(d0 + j,       a0);
        __stcs(d0 + j + 32,  a1);
        __stcs(d0 + j + 64,  a2);
        __stcs(d0 + j + 96,  a3);
        __stcs(d0 + j + 128, a4);
        __stcs(d0 + j + 160, a5);
        __stcs(d1 + j,       b0);
        __stcs(d1 + j + 32,  b1);
        __stcs(d1 + j + 64,  b2);
        __stcs(d1 + j + 96,  b3);
        __stcs(d1 + j + 128, b4);
        __stcs(d1 + j + 160, b5);

        // leftover float2: even rows at +960, odd rows at +192
        if (j == 0) {
            const long off = rfA + (par ? 192 : 960);
            __stcs((float2*)(outf + off), __ldcs((const float2*)(specf + off)));
        } else if (j == 1) {
            const long off = rfB + (par ? 192 : 960);
            __stcs((float2*)(outf + off), __ldcs((const float2*)(specf + off)));
        }
    }
}

extern "C" void kernel_launch(void* const* d_in, const int* in_sizes, int n_in,
                              void* d_out, int out_size)
{
    const float*  spec   = (const float*)d_in[0];
    const float4* coefs4 = (const float4*)d_in[1];
    float* out = (float*)d_out;

    df_op_kernel<<<(DF_B * DF_T) / 2, 128>>>(spec, coefs4, out);
}

// round 10
// speedup vs baseline: 1.0404x; 1.0050x over previous
#include <cuda_runtime.h>

// DfOp: out[b,t,f] = sum_{i=0..4} spec[b, t+i-4, f] * coefs[b, i, t, f] (complex) for f < 96
//       out[b,t,f] = spec[b,t,f]                                                 for f >= 96
// spec:  (8, 1, 4096, 481, 2) f32, coefs: (8, 5, 4096, 96, 2) f32
//
// Block = 160 threads, TWO rows of the SAME parity: {4k,4k+2} (even bid) or
// {4k+1,4k+3} (odd bid). Row parity block-uniform -> compile-time alignment.
//  tid 0..95   : filter, 2 bins/thread (5x LDG.128 coef + mixed spec loads)
//  tid 96..127 : copy float region [192,962) of row A (6x LDG.128 / thread)
//  tid 128..159: copy float region [192,962) of row B (6x LDG.128 / thread)

#define DF_B  8
#define DF_T  4096
#define DF_F  481
#define DF_NF 96
#define DF_FS 5
#define ROW_FLOATS (2 * DF_F)   // 962

template<int PAR>
__device__ __forceinline__ void do_filter(
    const float* __restrict__ specf,
    const float4* __restrict__ coefs4,
    float* __restrict__ outf,
    int row, int j)
{
    const int t = row & (DF_T - 1);
    const int b = row >> 12;
    const long rowf = (long)row * ROW_FLOATS;
    const int cbase = ((b * DF_FS) * DF_T + t) * 48 + j;
    const float* __restrict__ sp = specf + rowf + 4 * j;

    float re0 = 0.f, im0 = 0.f, re1 = 0.f, im1 = 0.f;
    if (t >= DF_FS - 1) {
        #pragma unroll
        for (int i = 0; i < DF_FS; i++) {
            float4 c = __ldcs(coefs4 + cbase + i * (DF_T * 48));
            const float* s = sp + (long)(i - (DF_FS - 1)) * ROW_FLOATS;
            float2 sa, sb;
            if (((i ^ PAR) & 1) == 0) {
                // tap base 16B-aligned: one LDG.128 covers both bins
                float4 v = *(const float4*)s;
                sa = make_float2(v.x, v.y);
                sb = make_float2(v.z, v.w);
            } else {
                sa = *(const float2*)s;
                sb = *(const float2*)(s + 2);
            }
            re0 = fmaf( sa.x, c.x, re0); re0 = fmaf(-sa.y, c.y, re0);
            im0 = fmaf( sa.x, c.y, im0); im0 = fmaf( sa.y, c.x, im0);
            re1 = fmaf( sb.x, c.z, re1); re1 = fmaf(-sb.y, c.w, re1);
            im1 = fmaf( sb.x, c.w, im1); im1 = fmaf( sb.y, c.z, im1);
        }
    } else {
        #pragma unroll
        for (int i = 0; i < DF_FS; i++) {
            if (t + i >= DF_FS - 1) {
                float4 c = __ldcs(coefs4 + cbase + i * (DF_T * 48));
                const float* s = sp + (long)(i - (DF_FS - 1)) * ROW_FLOATS;
                float2 sa = *(const float2*)(s);
                float2 sb = *(const float2*)(s + 2);
                re0 = fmaf( sa.x, c.x, re0); re0 = fmaf(-sa.y, c.y, re0);
                im0 = fmaf( sa.x, c.y, im0); im0 = fmaf( sa.y, c.x, im0);
                re1 = fmaf( sb.x, c.z, re1); re1 = fmaf(-sb.y, c.w, re1);
                im1 = fmaf( sb.x, c.w, im1); im1 = fmaf( sb.y, c.z, im1);
            }
        }
    }
    if (PAR == 0) {
        // output base 16B-aligned: single STG.128
        __stcs((float4*)(outf + rowf + 4 * j), make_float4(re0, im0, re1, im1));
    } else {
        __stcs((float2*)(outf + rowf + 4 * j),     make_float2(re0, im0));
        __stcs((float2*)(outf + rowf + 4 * j + 2), make_float2(re1, im1));
    }
}

__global__ __launch_bounds__(160) void df_op_kernel(
    const float* __restrict__ specf,
    const float4* __restrict__ coefs4,
    float* __restrict__ outf)
{
    const int bid  = blockIdx.x;
    const int par  = bid & 1;
    const int base = ((bid >> 1) << 2) + par;   // rows: base, base+2 (same parity)
    const int tid  = threadIdx.x;

    if (tid < 96) {
        const int row = base + ((tid >= 48) ? 2 : 0);
        const int j   = (tid >= 48) ? tid - 48 : tid;   // 0..47 -> bins 2j, 2j+1
        if (par == 0) do_filter<0>(specf, coefs4, outf, row, j);
        else          do_filter<1>(specf, coefs4, outf, row, j);
    } else {
        // ---------------- copy path: one row per warp ----------------
        const int  w    = (tid - 96) >> 5;              // 0 -> row base, 1 -> row base+2
        const int  j    = tid & 31;                     // 0..31
        const long rf   = (long)(base + 2 * w) * ROW_FLOATS;
        const int  start = 192 + 2 * par;               // 16B-aligned float4 base

        const float4* __restrict__ s = (const float4*)(specf + rf + start);
        float4* __restrict__       d = (float4*)(outf + rf + start);

        // 6 front-batched LDG.128 per thread
        float4 a0 = __ldcs(s + j);
        float4 a1 = __ldcs(s + j + 32);
        float4 a2 = __ldcs(s + j + 64);
        float4 a3 = __ldcs(s + j + 96);
        float4 a4 = __ldcs(s + j + 128);
        float4 a5 = __ldcs(s + j + 160);

        __stcs(d + j,       a0);
        __stcs(d + j + 32,  a1);
        __stcs(d + j + 64,  a2);
        __stcs(d + j + 96,  a3);
        __stcs(d + j + 128, a4);
        __stcs(d + j + 160, a5);

        // leftover float2: even rows at +960, odd rows at +192
        if (j == 0) {
            const long off = rf + (par ? 192 : 960);
            __stcs((float2*)(outf + off), __ldcs((const float2*)(specf + off)));
        }
    }
}

extern "C" void kernel_launch(void* const* d_in, const int* in_sizes, int n_in,
                              void* d_out, int out_size)
{
    const float*  spec   = (const float*)d_in[0];
    const float4* coefs4 = (const float4*)d_in[1];
    float* out = (float*)d_out;

    df_op_kernel<<<(DF_B * DF_T) / 2, 160>>>(spec, coefs4, out);
}